// round 11
// baseline (speedup 1.0000x reference)
#include <cuda_runtime.h>
#include <cuda_bf16.h>
#include <cstdint>

// Problem constants
#define BB 2
#define LL 2048
#define DD 1024
#define NH 16
#define HD 64
#define MM (BB*LL)      // 4096
#define N3 (3*DD)       // 3072
#define KK DD           // 1024

typedef unsigned long long u64;
typedef unsigned int u32;

// ---- tf32 mma.sync helpers ----
__device__ __forceinline__ u32 f2tf32(float f) {
    u32 r; asm("cvt.rna.tf32.f32 %0, %1;" : "=r"(r) : "f"(f)); return r;
}
__device__ __forceinline__ void mma_tf32(float& d0, float& d1, float& d2, float& d3,
                                         u32 a0, u32 a1, u32 a2, u32 a3,
                                         u32 b0, u32 b1) {
    asm volatile(
        "mma.sync.aligned.m16n8k8.row.col.f32.tf32.tf32.f32 "
        "{%0,%1,%2,%3}, {%4,%5,%6,%7}, {%8,%9}, {%0,%1,%2,%3};"
        : "+f"(d0), "+f"(d1), "+f"(d2), "+f"(d3)
        : "r"(a0), "r"(a1), "r"(a2), "r"(a3), "r"(b0), "r"(b1));
}
__device__ __forceinline__ float ex2(float x) {
    float y; asm("ex2.approx.f32 %0, %1;" : "=f"(y) : "f"(x)); return y;
}
__device__ __forceinline__ u32 smem_u32(const void* p) {
    u32 a;
    asm("{ .reg .u64 t; cvta.to.shared.u64 t, %1; cvt.u32.u64 %0, t; }" : "=r"(a) : "l"(p));
    return a;
}
__device__ __forceinline__ void ldsm_x4(u32& r0, u32& r1, u32& r2, u32& r3, u32 addr) {
    asm volatile("ldmatrix.sync.aligned.m8n8.x4.shared.b16 {%0,%1,%2,%3}, [%4];"
                 : "=r"(r0), "=r"(r1), "=r"(r2), "=r"(r3) : "r"(addr));
}

// Scratch for qkv = x @ W^T + b : [4096, 3072] fp32
__device__ float g_qkv[(size_t)MM * N3];

// ---------------------------------------------------------------------------
// Kernel 1: QKV GEMM, mma.sync tf32.
// K-chunk 8, double-buffered, smem stride 12 (16B-aligned rows AND LDSM
// conflict-free: 16B-group (3r + c/4) mod 8 distinct for r=0..7).
// 24.6 KB smem -> 2 CTAs/SM. 256 threads = 8 warps (2m x 4n), warp tile 64x32.
// ---------------------------------------------------------------------------
#define GST 12

__global__ __launch_bounds__(256, 2) void qkv_gemm_mma(
    const float* __restrict__ x,
    const float* __restrict__ W,
    const float* __restrict__ bias,
    float* __restrict__ C)
{
    __shared__ u32 sX[2 * 128 * GST];
    __shared__ u32 sW[2 * 128 * GST];
    __shared__ float sBias[128];

    const int bm = blockIdx.y * 128;
    const int bn = blockIdx.x * 128;
    const int tid  = threadIdx.x;
    const int wid  = tid >> 5;
    const int lane = tid & 31;
    const int wm = (wid >> 2) * 64;
    const int wn = (wid & 3) * 32;
    const int lr = lane >> 2;
    const int lc = lane & 3;

    // chunk load: 128 rows x 8 k = 256 float4; 1 per thread
    const int l_row = tid >> 1;      // 0..127
    const int l_f4  = tid & 1;       // 0..1

    const u32 sXa = smem_u32(sX);
    const u32 sWa = smem_u32(sW);

    // ldmatrix lane addressing
    const int lm  = lane >> 3;
    const int lrw = lane & 7;
    const int a_row = (lm & 1) * 8 + lrw;
    const int a_col = (lm >> 1) * 4;
    const int b_nt  = lm >> 1;
    const int b_col = (lm & 1) * 4;

    float d[4][4][4];
#pragma unroll
    for (int mt = 0; mt < 4; mt++)
#pragma unroll
        for (int nt = 0; nt < 4; nt++)
#pragma unroll
            for (int r = 0; r < 4; r++) d[mt][nt][r] = 0.f;

    if (tid < 128) sBias[tid] = bias[bn + tid];

    const float* xrow = x + (size_t)(bm + l_row) * KK + l_f4 * 4;
    const float* wrow = W + (size_t)(bn + l_row) * KK + l_f4 * 4;

    float4 px = *(const float4*)xrow;
    float4 pw = *(const float4*)wrow;
    *(uint4*)&sX[l_row * GST + l_f4 * 4] =
        make_uint4(f2tf32(px.x), f2tf32(px.y), f2tf32(px.z), f2tf32(px.w));
    *(uint4*)&sW[l_row * GST + l_f4 * 4] =
        make_uint4(f2tf32(pw.x), f2tf32(pw.y), f2tf32(pw.z), f2tf32(pw.w));
    __syncthreads();

    const int NC = KK / 8;   // 128 chunks
#pragma unroll 2
    for (int c = 0; c < NC; c++) {
        if (c + 1 < NC) {
            px = *(const float4*)(xrow + (c + 1) * 8);
            pw = *(const float4*)(wrow + (c + 1) * 8);
        }

        const u32 bufX = sXa + (u32)((c & 1) * 128 * GST * 4);
        const u32 bufW = sWa + (u32)((c & 1) * 128 * GST * 4);

        u32 af[4][4];
        u32 bf[4][2];
#pragma unroll
        for (int mt = 0; mt < 4; mt++) {
            u32 addr = bufX + (u32)(((wm + mt * 16 + a_row) * GST + a_col) * 4);
            ldsm_x4(af[mt][0], af[mt][1], af[mt][2], af[mt][3], addr);
        }
#pragma unroll
        for (int np = 0; np < 2; np++) {
            u32 addr = bufW + (u32)(((wn + (np * 2 + b_nt) * 8 + lrw) * GST + b_col) * 4);
            ldsm_x4(bf[np * 2][0], bf[np * 2][1], bf[np * 2 + 1][0], bf[np * 2 + 1][1], addr);
        }
#pragma unroll
        for (int mt = 0; mt < 4; mt++)
#pragma unroll
            for (int nt = 0; nt < 4; nt++)
                mma_tf32(d[mt][nt][0], d[mt][nt][1], d[mt][nt][2], d[mt][nt][3],
                         af[mt][0], af[mt][1], af[mt][2], af[mt][3],
                         bf[nt][0], bf[nt][1]);

        if (c + 1 < NC) {
            u32* dX = sX + ((c + 1) & 1) * 128 * GST;
            u32* dW = sW + ((c + 1) & 1) * 128 * GST;
            *(uint4*)&dX[l_row * GST + l_f4 * 4] =
                make_uint4(f2tf32(px.x), f2tf32(px.y), f2tf32(px.z), f2tf32(px.w));
            *(uint4*)&dW[l_row * GST + l_f4 * 4] =
                make_uint4(f2tf32(pw.x), f2tf32(pw.y), f2tf32(pw.z), f2tf32(pw.w));
        }
        __syncthreads();
    }

#pragma unroll
    for (int mt = 0; mt < 4; mt++) {
        const int r0 = bm + wm + mt * 16 + lr;
#pragma unroll
        for (int nt = 0; nt < 4; nt++) {
            const int cl = wn + nt * 8 + lc * 2;
            float2 v0, v1;
            v0.x = d[mt][nt][0] + sBias[cl];
            v0.y = d[mt][nt][1] + sBias[cl + 1];
            v1.x = d[mt][nt][2] + sBias[cl];
            v1.y = d[mt][nt][3] + sBias[cl + 1];
            *(float2*)(C + (size_t)r0 * N3 + bn + cl) = v0;
            *(float2*)(C + (size_t)(r0 + 8) * N3 + bn + cl) = v1;
        }
    }
}

// ---------------------------------------------------------------------------
// Kernel 2: flash attention, mma.sync tf32, kv-tile 32, double-buffered,
// ldmatrix K fragments, shuffle-based P relayout (R7 structure) + corr-skip.
// ---------------------------------------------------------------------------
#define KSTR 68
#define VSTR 72
#define KV 32

__global__ __launch_bounds__(256) void attn_mma(
    const float* __restrict__ qkv,   // [MM, N3]
    float* __restrict__ out)         // [MM, DD]
{
    __shared__ u32 pool[2 * KV * KSTR + 2 * KV * VSTR];   // 35840 B
    u32* sK = pool;
    u32* sV = pool + 2 * KV * KSTR;
    const u32 sKa = smem_u32(sK);

    const int qtile = blockIdx.x;
    const int h     = blockIdx.y;
    const int b     = blockIdx.z;
    const int tid   = threadIdx.x;
    const int wid   = tid >> 5;
    const int lane  = tid & 31;
    const int lr    = lane >> 2;
    const int lc    = lane & 3;
    const int lm    = lane >> 3;
    const int lrw   = lane & 7;

    const float qs = 0.18033688011110793f;  // 0.125 * log2(e)

    const int l_row = tid >> 3;          // 0..31 (kv row)
    const int l_f4h = tid & 7;           // 0..7

    // ---- Q fragments resident ----
    const int row0 = qtile * 128 + wid * 16;
    const float* q0 = qkv + ((size_t)(b * LL + row0 + lr)) * N3 + h * HD;
    const float* q1 = q0 + 8 * (size_t)N3;
    u32 qa[8][4];
#pragma unroll
    for (int kst = 0; kst < 8; kst++) {
        int kk = kst * 8;
        qa[kst][0] = f2tf32(q0[kk + lc    ] * qs);
        qa[kst][1] = f2tf32(q1[kk + lc    ] * qs);
        qa[kst][2] = f2tf32(q0[kk + lc + 4] * qs);
        qa[kst][3] = f2tf32(q1[kk + lc + 4] * qs);
    }

    float o[8][4];
#pragma unroll
    for (int dt = 0; dt < 8; dt++)
#pragma unroll
        for (int r = 0; r < 4; r++) o[dt][r] = 0.f;
    float m_a = -1e30f, m_b = -1e30f;
    float l_a = 0.f,    l_b = 0.f;

    const float* kvbase = qkv + (size_t)b * LL * N3 + DD + h * HD;

    float4 pk[2], pv[2];
#pragma unroll
    for (int i = 0; i < 2; i++) {
        const float* kp = kvbase + (size_t)l_row * N3 + (l_f4h + i * 8) * 4;
        pk[i] = *(const float4*)kp;
        pv[i] = *(const float4*)(kp + DD);
    }
#pragma unroll
    for (int i = 0; i < 2; i++) {
        int f4 = l_f4h + i * 8;
        *(uint4*)&sK[l_row * KSTR + f4 * 4] =
            make_uint4(f2tf32(pk[i].x), f2tf32(pk[i].y), f2tf32(pk[i].z), f2tf32(pk[i].w));
        *(uint4*)&sV[l_row * VSTR + f4 * 4] =
            make_uint4(f2tf32(pv[i].x), f2tf32(pv[i].y), f2tf32(pv[i].z), f2tf32(pv[i].w));
    }
    __syncthreads();

    const int NT = LL / KV;   // 64
    for (int kt = 0; kt < NT; kt++) {
        if (kt + 1 < NT) {
            const float* tb = kvbase + (size_t)((kt + 1) * KV) * N3;
#pragma unroll
            for (int i = 0; i < 2; i++) {
                const float* kp = tb + (size_t)l_row * N3 + (l_f4h + i * 8) * 4;
                pk[i] = *(const float4*)kp;
                pv[i] = *(const float4*)(kp + DD);
            }
        }

        const u32 bufK = sKa + (u32)((kt & 1) * KV * KSTR * 4);
        u32* bufV = sV + (kt & 1) * KV * VSTR;

        // ---- S = Q K^T ----
        float s[4][4];
#pragma unroll
        for (int nt = 0; nt < 4; nt++)
#pragma unroll
            for (int r = 0; r < 4; r++) s[nt][r] = 0.f;

#pragma unroll
        for (int kst = 0; kst < 8; kst++) {
            const int kk = kst * 8;
            u32 bf[4][2];
#pragma unroll
            for (int np = 0; np < 2; np++) {
                int nt0 = np * 2 + (lm >> 1);
                u32 addr = bufK + (u32)(((nt0 * 8 + lrw) * KSTR + kk + (lm & 1) * 4) * 4);
                ldsm_x4(bf[np * 2][0], bf[np * 2][1], bf[np * 2 + 1][0], bf[np * 2 + 1][1], addr);
            }
#pragma unroll
            for (int nt = 0; nt < 4; nt++)
                mma_tf32(s[nt][0], s[nt][1], s[nt][2], s[nt][3],
                         qa[kst][0], qa[kst][1], qa[kst][2], qa[kst][3],
                         bf[nt][0], bf[nt][1]);
        }

        // ---- online softmax ----
        float mx_a = -1e30f, mx_b = -1e30f;
#pragma unroll
        for (int nt = 0; nt < 4; nt++) {
            mx_a = fmaxf(mx_a, fmaxf(s[nt][0], s[nt][1]));
            mx_b = fmaxf(mx_b, fmaxf(s[nt][2], s[nt][3]));
        }
        mx_a = fmaxf(mx_a, __shfl_xor_sync(0xffffffffu, mx_a, 1));
        mx_a = fmaxf(mx_a, __shfl_xor_sync(0xffffffffu, mx_a, 2));
        mx_b = fmaxf(mx_b, __shfl_xor_sync(0xffffffffu, mx_b, 1));
        mx_b = fmaxf(mx_b, __shfl_xor_sync(0xffffffffu, mx_b, 2));

        const bool need = (mx_a > m_a) || (mx_b > m_b);
        if (__any_sync(0xffffffffu, need)) {
            float nm_a = fmaxf(m_a, mx_a);
            float nm_b = fmaxf(m_b, mx_b);
            float ca = ex2(m_a - nm_a);
            float cb = ex2(m_b - nm_b);
            m_a = nm_a; m_b = nm_b;
            l_a *= ca;  l_b *= cb;
#pragma unroll
            for (int dt = 0; dt < 8; dt++) {
                o[dt][0] *= ca; o[dt][1] *= ca;
                o[dt][2] *= cb; o[dt][3] *= cb;
            }
        }

        u32 p[4][4];
#pragma unroll
        for (int nt = 0; nt < 4; nt++) {
            float p0 = ex2(s[nt][0] - m_a);
            float p1 = ex2(s[nt][1] - m_a);
            float p2 = ex2(s[nt][2] - m_b);
            float p3 = ex2(s[nt][3] - m_b);
            l_a += p0 + p1;
            l_b += p2 + p3;
            p[nt][0] = f2tf32(p0); p[nt][1] = f2tf32(p1);
            p[nt][2] = f2tf32(p2); p[nt][3] = f2tf32(p3);
        }

        // ---- O += P V (shuffle-based P relayout) ----
        const int s0 = lr * 4 + (lc >> 1);
        const int s2 = s0 + 2;
        const bool odd = (lc & 1);
#pragma unroll
        for (int jt = 0; jt < 4; jt++) {
            u32 v00 = __shfl_sync(0xffffffffu, p[jt][0], s0);
            u32 v01 = __shfl_sync(0xffffffffu, p[jt][1], s0);
            u32 v20 = __shfl_sync(0xffffffffu, p[jt][0], s2);
            u32 v21 = __shfl_sync(0xffffffffu, p[jt][1], s2);
            u32 w00 = __shfl_sync(0xffffffffu, p[jt][2], s0);
            u32 w01 = __shfl_sync(0xffffffffu, p[jt][3], s0);
            u32 w20 = __shfl_sync(0xffffffffu, p[jt][2], s2);
            u32 w21 = __shfl_sync(0xffffffffu, p[jt][3], s2);
            u32 a0 = odd ? v01 : v00;
            u32 a2 = odd ? v21 : v20;
            u32 a1 = odd ? w01 : w00;
            u32 a3 = odd ? w21 : w20;
#pragma unroll
            for (int dt = 0; dt < 8; dt++) {
                u32 b0 = bufV[(jt * 8 + lc    ) * VSTR + dt * 8 + lr];
                u32 b1 = bufV[(jt * 8 + lc + 4) * VSTR + dt * 8 + lr];
                mma_tf32(o[dt][0], o[dt][1], o[dt][2], o[dt][3],
                         a0, a1, a2, a3, b0, b1);
            }
        }

        // stage next tile into other buffers
        if (kt + 1 < NT) {
            u32* dK = sK + ((kt + 1) & 1) * KV * KSTR;
            u32* dV = sV + ((kt + 1) & 1) * KV * VSTR;
#pragma unroll
            for (int i = 0; i < 2; i++) {
                int f4 = l_f4h + i * 8;
                *(uint4*)&dK[l_row * KSTR + f4 * 4] =
                    make_uint4(f2tf32(pk[i].x), f2tf32(pk[i].y), f2tf32(pk[i].z), f2tf32(pk[i].w));
                *(uint4*)&dV[l_row * VSTR + f4 * 4] =
                    make_uint4(f2tf32(pv[i].x), f2tf32(pv[i].y), f2tf32(pv[i].z), f2tf32(pv[i].w));
            }
        }
        __syncthreads();
    }

    // ---- final reduce + normalize ----
    l_a += __shfl_xor_sync(0xffffffffu, l_a, 1);
    l_a += __shfl_xor_sync(0xffffffffu, l_a, 2);
    l_b += __shfl_xor_sync(0xffffffffu, l_b, 1);
    l_b += __shfl_xor_sync(0xffffffffu, l_b, 2);
    float inv_a = 1.f / l_a;
    float inv_b = 1.f / l_b;

    // ---- stage O to smem then coalesced store ----
    float* stage = (float*)pool;   // 128 x 68 floats = 34816 B <= pool
    {
        const int ra = wid * 16 + lr;
        const int rb = ra + 8;
#pragma unroll
        for (int dt = 0; dt < 8; dt++) {
            float2 va, vb;
            va.x = o[dt][0] * inv_a; va.y = o[dt][1] * inv_a;
            vb.x = o[dt][2] * inv_b; vb.y = o[dt][3] * inv_b;
            *(float2*)&stage[ra * 68 + dt * 8 + lc * 2] = va;
            *(float2*)&stage[rb * 68 + dt * 8 + lc * 2] = vb;
        }
    }
    __syncthreads();
    {
        const int cr = tid >> 4;
        const int cc = tid & 15;
#pragma unroll
        for (int pass = 0; pass < 8; pass++) {
            int row = pass * 16 + cr;
            float4 v = *(const float4*)&stage[row * 68 + cc * 4];
            *(float4*)(out + ((size_t)(b * LL + qtile * 128 + row)) * DD + h * HD + cc * 4) = v;
        }
    }
}

// ---------------------------------------------------------------------------
extern "C" void kernel_launch(void* const* d_in, const int* in_sizes, int n_in,
                              void* d_out, int out_size)
{
    const float* x    = (const float*)d_in[0];
    const float* W    = (const float*)d_in[1];
    const float* bias = (const float*)d_in[2];
    float* out = (float*)d_out;

    float* qkv;
    cudaGetSymbolAddress((void**)&qkv, g_qkv);

    dim3 ggrid(N3 / 128, MM / 128);  // (24, 32)
    qkv_gemm_mma<<<ggrid, 256>>>(x, W, bias, qkv);

    dim3 agrid(LL / 128, NH, BB);    // (16, 16, 2)
    attn_mma<<<agrid, 256>>>(qkv, out);
}

// round 12
// speedup vs baseline: 1.1233x; 1.1233x over previous
#include <cuda_runtime.h>
#include <cuda_bf16.h>
#include <cstdint>

// Problem constants
#define BB 2
#define LL 2048
#define DD 1024
#define NH 16
#define HD 64
#define MM (BB*LL)      // 4096
#define N3 (3*DD)       // 3072
#define KK DD           // 1024

typedef unsigned long long u64;
typedef unsigned int u32;

// ---- tf32 mma.sync helpers ----
__device__ __forceinline__ u32 f2tf32(float f) {
    u32 r; asm("cvt.rna.tf32.f32 %0, %1;" : "=r"(r) : "f"(f)); return r;
}
__device__ __forceinline__ void mma_tf32(float& d0, float& d1, float& d2, float& d3,
                                         u32 a0, u32 a1, u32 a2, u32 a3,
                                         u32 b0, u32 b1) {
    asm volatile(
        "mma.sync.aligned.m16n8k8.row.col.f32.tf32.tf32.f32 "
        "{%0,%1,%2,%3}, {%4,%5,%6,%7}, {%8,%9}, {%0,%1,%2,%3};"
        : "+f"(d0), "+f"(d1), "+f"(d2), "+f"(d3)
        : "r"(a0), "r"(a1), "r"(a2), "r"(a3), "r"(b0), "r"(b1));
}
__device__ __forceinline__ float ex2(float x) {
    float y; asm("ex2.approx.f32 %0, %1;" : "=f"(y) : "f"(x)); return y;
}
__device__ __forceinline__ u32 smem_u32(const void* p) {
    u32 a;
    asm("{ .reg .u64 t; cvta.to.shared.u64 t, %1; cvt.u32.u64 %0, t; }" : "=r"(a) : "l"(p));
    return a;
}
__device__ __forceinline__ void ldsm_x4(u32& r0, u32& r1, u32& r2, u32& r3, u32 addr) {
    asm volatile("ldmatrix.sync.aligned.m8n8.x4.shared.b16 {%0,%1,%2,%3}, [%4];"
                 : "=r"(r0), "=r"(r1), "=r"(r2), "=r"(r3) : "r"(addr));
}
__device__ __forceinline__ void cpa16(u32 dst, const void* src) {
    asm volatile("cp.async.cg.shared.global [%0], [%1], 16;" :: "r"(dst), "l"(src) : "memory");
}
#define CP_COMMIT() asm volatile("cp.async.commit_group;" ::: "memory")
#define CP_WAIT1()  asm volatile("cp.async.wait_group 1;" ::: "memory")

// Scratch: qkv [4096,3072] f32 (tf32-rounded values); pre-rounded x and W.
__device__ float g_qkv[(size_t)MM * N3];
__device__ float g_xc[(size_t)MM * KK];
__device__ float g_wc[(size_t)N3 * KK];

// ---------------------------------------------------------------------------
// Kernel 0: pre-pass — rna-round x and W to tf32 values (stored as f32 bits).
// ---------------------------------------------------------------------------
__global__ void cvt_prepass(const float* __restrict__ x, const float* __restrict__ W,
                            float* __restrict__ xc, float* __restrict__ wc)
{
    const size_t nx4 = (size_t)MM * KK / 4;      // 1048576
    const size_t nw4 = (size_t)N3 * KK / 4;      // 786432
    size_t i = (size_t)blockIdx.x * blockDim.x + threadIdx.x;
    if (i < nx4) {
        float4 v = ((const float4*)x)[i];
        uint4 r = make_uint4(f2tf32(v.x), f2tf32(v.y), f2tf32(v.z), f2tf32(v.w));
        ((uint4*)xc)[i] = r;
    } else if (i < nx4 + nw4) {
        size_t j = i - nx4;
        float4 v = ((const float4*)W)[j];
        uint4 r = make_uint4(f2tf32(v.x), f2tf32(v.y), f2tf32(v.z), f2tf32(v.w));
        ((uint4*)wc)[j] = r;
    }
}

// ---------------------------------------------------------------------------
// Kernel 1: QKV GEMM, mma.sync tf32, 3-stage cp.async pipeline, chunk 8.
// smem stride 12 (16B-aligned rows, LDSM conflict-free). 37 KB -> 2 CTAs/SM.
// Inputs pre-rounded -> no cvt in hot loop. Epilogue rounds output to tf32.
// ---------------------------------------------------------------------------
#define GST 12

__global__ __launch_bounds__(256, 2) void qkv_gemm_mma(
    const float* __restrict__ x,     // pre-rounded [MM, KK]
    const float* __restrict__ W,     // pre-rounded [N3, KK]
    const float* __restrict__ bias,
    float* __restrict__ C)           // [MM, N3] (tf32-rounded values)
{
    __shared__ u32 sX[3 * 128 * GST];
    __shared__ u32 sW[3 * 128 * GST];
    __shared__ float sBias[128];

    const int bm = blockIdx.y * 128;
    const int bn = blockIdx.x * 128;
    const int tid  = threadIdx.x;
    const int wid  = tid >> 5;
    const int lane = tid & 31;
    const int wm = (wid >> 2) * 64;
    const int wn = (wid & 3) * 32;
    const int lr = lane >> 2;
    const int lc = lane & 3;

    const int l_row = tid >> 1;      // 0..127
    const int l_f4  = tid & 1;       // 0..1

    const u32 sXa = smem_u32(sX);
    const u32 sWa = smem_u32(sW);
    const u32 SSZ = 128 * GST * 4;   // bytes per stage
    const u32 dX0 = sXa + (u32)((l_row * GST + l_f4 * 4) * 4);
    const u32 dW0 = sWa + (u32)((l_row * GST + l_f4 * 4) * 4);
    const float* xsrc = x + (size_t)(bm + l_row) * KK + l_f4 * 4;
    const float* wsrc = W + (size_t)(bn + l_row) * KK + l_f4 * 4;

    // ldmatrix lane addressing
    const int lm  = lane >> 3;
    const int lrw = lane & 7;
    const int a_row = (lm & 1) * 8 + lrw;
    const int a_col = (lm >> 1) * 4;
    const int b_nt  = lm >> 1;
    const int b_col = (lm & 1) * 4;

    float d[4][4][4];
#pragma unroll
    for (int mt = 0; mt < 4; mt++)
#pragma unroll
        for (int nt = 0; nt < 4; nt++)
#pragma unroll
            for (int r = 0; r < 4; r++) d[mt][nt][r] = 0.f;

    if (tid < 128) sBias[tid] = bias[bn + tid];

    // prologue: stages 0 and 1 in flight
#pragma unroll
    for (int s = 0; s < 2; s++) {
        cpa16(dX0 + s * SSZ, xsrc + s * 8);
        cpa16(dW0 + s * SSZ, wsrc + s * 8);
        CP_COMMIT();
    }

    const int NC = KK / 8;   // 128 chunks
#pragma unroll 3
    for (int c = 0; c < NC; c++) {
        CP_WAIT1();
        __syncthreads();

        const int st = c % 3;
        const u32 bufX = sXa + (u32)(st * SSZ);
        const u32 bufW = sWa + (u32)(st * SSZ);

        u32 af[4][4];
        u32 bf[4][2];
#pragma unroll
        for (int mt = 0; mt < 4; mt++) {
            u32 addr = bufX + (u32)(((wm + mt * 16 + a_row) * GST + a_col) * 4);
            ldsm_x4(af[mt][0], af[mt][1], af[mt][2], af[mt][3], addr);
        }
#pragma unroll
        for (int np = 0; np < 2; np++) {
            u32 addr = bufW + (u32)(((wn + (np * 2 + b_nt) * 8 + lrw) * GST + b_col) * 4);
            ldsm_x4(bf[np * 2][0], bf[np * 2][1], bf[np * 2 + 1][0], bf[np * 2 + 1][1], addr);
        }
#pragma unroll
        for (int mt = 0; mt < 4; mt++)
#pragma unroll
            for (int nt = 0; nt < 4; nt++)
                mma_tf32(d[mt][nt][0], d[mt][nt][1], d[mt][nt][2], d[mt][nt][3],
                         af[mt][0], af[mt][1], af[mt][2], af[mt][3],
                         bf[nt][0], bf[nt][1]);

        if (c + 2 < NC) {
            const int sn = (c + 2) % 3;
            cpa16(dX0 + sn * SSZ, xsrc + (c + 2) * 8);
            cpa16(dW0 + sn * SSZ, wsrc + (c + 2) * 8);
        }
        CP_COMMIT();
    }

    // Epilogue: bias add, round to tf32 value, store (so attention can use raw bits).
#pragma unroll
    for (int mt = 0; mt < 4; mt++) {
        const int r0 = bm + wm + mt * 16 + lr;
#pragma unroll
        for (int nt = 0; nt < 4; nt++) {
            const int cl = wn + nt * 8 + lc * 2;
            float2 v0, v1;
            v0.x = __uint_as_float(f2tf32(d[mt][nt][0] + sBias[cl]));
            v0.y = __uint_as_float(f2tf32(d[mt][nt][1] + sBias[cl + 1]));
            v1.x = __uint_as_float(f2tf32(d[mt][nt][2] + sBias[cl]));
            v1.y = __uint_as_float(f2tf32(d[mt][nt][3] + sBias[cl + 1]));
            *(float2*)(C + (size_t)r0 * N3 + bn + cl) = v0;
            *(float2*)(C + (size_t)(r0 + 8) * N3 + bn + cl) = v1;
        }
    }
}

// ---------------------------------------------------------------------------
// Kernel 2: flash attention, mma.sync tf32 (R7 structure: kv-tile 32,
// double-buffered reg-prefetch, ldmatrix K frags, shuffle P relayout).
// K/V already tf32-valued -> no cvt on the staging path.
// ---------------------------------------------------------------------------
#define KSTR 68
#define VSTR 72
#define KV 32

__global__ __launch_bounds__(256) void attn_mma(
    const float* __restrict__ qkv,   // [MM, N3] tf32-valued
    float* __restrict__ out)         // [MM, DD]
{
    __shared__ u32 pool[2 * KV * KSTR + 2 * KV * VSTR];   // 35840 B
    u32* sK = pool;
    u32* sV = pool + 2 * KV * KSTR;
    const u32 sKa = smem_u32(sK);

    const int qtile = blockIdx.x;
    const int h     = blockIdx.y;
    const int b     = blockIdx.z;
    const int tid   = threadIdx.x;
    const int wid   = tid >> 5;
    const int lane  = tid & 31;
    const int lr    = lane >> 2;
    const int lc    = lane & 3;
    const int lm    = lane >> 3;
    const int lrw   = lane & 7;

    const float qs = 0.18033688011110793f;  // 0.125 * log2(e)

    const int l_row = tid >> 3;          // 0..31 (kv row)
    const int l_f4h = tid & 7;           // 0..7

    // ---- Q fragments resident ----
    const int row0 = qtile * 128 + wid * 16;
    const float* q0 = qkv + ((size_t)(b * LL + row0 + lr)) * N3 + h * HD;
    const float* q1 = q0 + 8 * (size_t)N3;
    u32 qa[8][4];
#pragma unroll
    for (int kst = 0; kst < 8; kst++) {
        int kk = kst * 8;
        qa[kst][0] = f2tf32(q0[kk + lc    ] * qs);
        qa[kst][1] = f2tf32(q1[kk + lc    ] * qs);
        qa[kst][2] = f2tf32(q0[kk + lc + 4] * qs);
        qa[kst][3] = f2tf32(q1[kk + lc + 4] * qs);
    }

    float o[8][4];
#pragma unroll
    for (int dt = 0; dt < 8; dt++)
#pragma unroll
        for (int r = 0; r < 4; r++) o[dt][r] = 0.f;
    float m_a = -1e30f, m_b = -1e30f;
    float l_a = 0.f,    l_b = 0.f;

    const float* kvbase = qkv + (size_t)b * LL * N3 + DD + h * HD;

    float4 pk[2], pv[2];
#pragma unroll
    for (int i = 0; i < 2; i++) {
        const float* kp = kvbase + (size_t)l_row * N3 + (l_f4h + i * 8) * 4;
        pk[i] = *(const float4*)kp;
        pv[i] = *(const float4*)(kp + DD);
    }
#pragma unroll
    for (int i = 0; i < 2; i++) {
        int f4 = l_f4h + i * 8;
        *(uint4*)&sK[l_row * KSTR + f4 * 4] =
            make_uint4(__float_as_uint(pk[i].x), __float_as_uint(pk[i].y),
                       __float_as_uint(pk[i].z), __float_as_uint(pk[i].w));
        *(uint4*)&sV[l_row * VSTR + f4 * 4] =
            make_uint4(__float_as_uint(pv[i].x), __float_as_uint(pv[i].y),
                       __float_as_uint(pv[i].z), __float_as_uint(pv[i].w));
    }
    __syncthreads();

    const int NT = LL / KV;   // 64
    for (int kt = 0; kt < NT; kt++) {
        if (kt + 1 < NT) {
            const float* tb = kvbase + (size_t)((kt + 1) * KV) * N3;
#pragma unroll
            for (int i = 0; i < 2; i++) {
                const float* kp = tb + (size_t)l_row * N3 + (l_f4h + i * 8) * 4;
                pk[i] = *(const float4*)kp;
                pv[i] = *(const float4*)(kp + DD);
            }
        }

        const u32 bufK = sKa + (u32)((kt & 1) * KV * KSTR * 4);
        u32* bufV = sV + (kt & 1) * KV * VSTR;

        // ---- S = Q K^T ----
        float s[4][4];
#pragma unroll
        for (int nt = 0; nt < 4; nt++)
#pragma unroll
            for (int r = 0; r < 4; r++) s[nt][r] = 0.f;

#pragma unroll
        for (int kst = 0; kst < 8; kst++) {
            const int kk = kst * 8;
            u32 bf[4][2];
#pragma unroll
            for (int np = 0; np < 2; np++) {
                int nt0 = np * 2 + (lm >> 1);
                u32 addr = bufK + (u32)(((nt0 * 8 + lrw) * KSTR + kk + (lm & 1) * 4) * 4);
                ldsm_x4(bf[np * 2][0], bf[np * 2][1], bf[np * 2 + 1][0], bf[np * 2 + 1][1], addr);
            }
#pragma unroll
            for (int nt = 0; nt < 4; nt++)
                mma_tf32(s[nt][0], s[nt][1], s[nt][2], s[nt][3],
                         qa[kst][0], qa[kst][1], qa[kst][2], qa[kst][3],
                         bf[nt][0], bf[nt][1]);
        }

        // ---- online softmax ----
        float mx_a = -1e30f, mx_b = -1e30f;
#pragma unroll
        for (int nt = 0; nt < 4; nt++) {
            mx_a = fmaxf(mx_a, fmaxf(s[nt][0], s[nt][1]));
            mx_b = fmaxf(mx_b, fmaxf(s[nt][2], s[nt][3]));
        }
        mx_a = fmaxf(mx_a, __shfl_xor_sync(0xffffffffu, mx_a, 1));
        mx_a = fmaxf(mx_a, __shfl_xor_sync(0xffffffffu, mx_a, 2));
        mx_b = fmaxf(mx_b, __shfl_xor_sync(0xffffffffu, mx_b, 1));
        mx_b = fmaxf(mx_b, __shfl_xor_sync(0xffffffffu, mx_b, 2));

        float nm_a = fmaxf(m_a, mx_a);
        float nm_b = fmaxf(m_b, mx_b);
        float ca = ex2(m_a - nm_a);
        float cb = ex2(m_b - nm_b);
        m_a = nm_a; m_b = nm_b;
        l_a *= ca;  l_b *= cb;
#pragma unroll
        for (int dt = 0; dt < 8; dt++) {
            o[dt][0] *= ca; o[dt][1] *= ca;
            o[dt][2] *= cb; o[dt][3] *= cb;
        }

        u32 p[4][4];
#pragma unroll
        for (int nt = 0; nt < 4; nt++) {
            float p0 = ex2(s[nt][0] - m_a);
            float p1 = ex2(s[nt][1] - m_a);
            float p2 = ex2(s[nt][2] - m_b);
            float p3 = ex2(s[nt][3] - m_b);
            l_a += p0 + p1;
            l_b += p2 + p3;
            p[nt][0] = f2tf32(p0); p[nt][1] = f2tf32(p1);
            p[nt][2] = f2tf32(p2); p[nt][3] = f2tf32(p3);
        }

        // ---- O += P V (shuffle-based P relayout) ----
        const int s0 = lr * 4 + (lc >> 1);
        const int s2 = s0 + 2;
        const bool odd = (lc & 1);
#pragma unroll
        for (int jt = 0; jt < 4; jt++) {
            u32 v00 = __shfl_sync(0xffffffffu, p[jt][0], s0);
            u32 v01 = __shfl_sync(0xffffffffu, p[jt][1], s0);
            u32 v20 = __shfl_sync(0xffffffffu, p[jt][0], s2);
            u32 v21 = __shfl_sync(0xffffffffu, p[jt][1], s2);
            u32 w00 = __shfl_sync(0xffffffffu, p[jt][2], s0);
            u32 w01 = __shfl_sync(0xffffffffu, p[jt][3], s0);
            u32 w20 = __shfl_sync(0xffffffffu, p[jt][2], s2);
            u32 w21 = __shfl_sync(0xffffffffu, p[jt][3], s2);
            u32 a0 = odd ? v01 : v00;
            u32 a2 = odd ? v21 : v20;
            u32 a1 = odd ? w01 : w00;
            u32 a3 = odd ? w21 : w20;
#pragma unroll
            for (int dt = 0; dt < 8; dt++) {
                u32 b0 = bufV[(jt * 8 + lc    ) * VSTR + dt * 8 + lr];
                u32 b1 = bufV[(jt * 8 + lc + 4) * VSTR + dt * 8 + lr];
                mma_tf32(o[dt][0], o[dt][1], o[dt][2], o[dt][3],
                         a0, a1, a2, a3, b0, b1);
            }
        }

        // stage next tile into other buffers
        if (kt + 1 < NT) {
            u32* dK = sK + ((kt + 1) & 1) * KV * KSTR;
            u32* dV = sV + ((kt + 1) & 1) * KV * VSTR;
#pragma unroll
            for (int i = 0; i < 2; i++) {
                int f4 = l_f4h + i * 8;
                *(uint4*)&dK[l_row * KSTR + f4 * 4] =
                    make_uint4(__float_as_uint(pk[i].x), __float_as_uint(pk[i].y),
                               __float_as_uint(pk[i].z), __float_as_uint(pk[i].w));
                *(uint4*)&dV[l_row * VSTR + f4 * 4] =
                    make_uint4(__float_as_uint(pv[i].x), __float_as_uint(pv[i].y),
                               __float_as_uint(pv[i].z), __float_as_uint(pv[i].w));
            }
        }
        __syncthreads();
    }

    // ---- final reduce + normalize ----
    l_a += __shfl_xor_sync(0xffffffffu, l_a, 1);
    l_a += __shfl_xor_sync(0xffffffffu, l_a, 2);
    l_b += __shfl_xor_sync(0xffffffffu, l_b, 1);
    l_b += __shfl_xor_sync(0xffffffffu, l_b, 2);
    float inv_a = 1.f / l_a;
    float inv_b = 1.f / l_b;

    // ---- stage O to smem then coalesced store ----
    float* stage = (float*)pool;   // 128 x 68 floats = 34816 B <= pool
    {
        const int ra = wid * 16 + lr;
        const int rb = ra + 8;
#pragma unroll
        for (int dt = 0; dt < 8; dt++) {
            float2 va, vb;
            va.x = o[dt][0] * inv_a; va.y = o[dt][1] * inv_a;
            vb.x = o[dt][2] * inv_b; vb.y = o[dt][3] * inv_b;
            *(float2*)&stage[ra * 68 + dt * 8 + lc * 2] = va;
            *(float2*)&stage[rb * 68 + dt * 8 + lc * 2] = vb;
        }
    }
    __syncthreads();
    {
        const int cr = tid >> 4;
        const int cc = tid & 15;
#pragma unroll
        for (int pass = 0; pass < 8; pass++) {
            int row = pass * 16 + cr;
            float4 v = *(const float4*)&stage[row * 68 + cc * 4];
            *(float4*)(out + ((size_t)(b * LL + qtile * 128 + row)) * DD + h * HD + cc * 4) = v;
        }
    }
}

// ---------------------------------------------------------------------------
extern "C" void kernel_launch(void* const* d_in, const int* in_sizes, int n_in,
                              void* d_out, int out_size)
{
    const float* x    = (const float*)d_in[0];
    const float* W    = (const float*)d_in[1];
    const float* bias = (const float*)d_in[2];
    float* out = (float*)d_out;

    float *qkv, *xc, *wc;
    cudaGetSymbolAddress((void**)&qkv, g_qkv);
    cudaGetSymbolAddress((void**)&xc,  g_xc);
    cudaGetSymbolAddress((void**)&wc,  g_wc);

    const size_t nf4 = ((size_t)MM * KK + (size_t)N3 * KK) / 4;  // 1835008
    cvt_prepass<<<(unsigned)((nf4 + 255) / 256), 256>>>(x, W, xc, wc);

    dim3 ggrid(N3 / 128, MM / 128);  // (24, 32)
    qkv_gemm_mma<<<ggrid, 256>>>(xc, wc, bias, qkv);

    dim3 agrid(LL / 128, NH, BB);    // (16, 16, 2)
    attn_mma<<<agrid, 256>>>(qkv, out);
}

// round 13
// speedup vs baseline: 1.1347x; 1.0101x over previous
#include <cuda_runtime.h>
#include <cuda_bf16.h>
#include <cstdint>

// Problem constants
#define BB 2
#define LL 2048
#define DD 1024
#define NH 16
#define HD 64
#define MM (BB*LL)      // 4096
#define N3 (3*DD)       // 3072
#define KK DD           // 1024

typedef unsigned long long u64;
typedef unsigned int u32;

// ---- tf32 mma.sync helpers ----
__device__ __forceinline__ u32 f2tf32(float f) {
    u32 r; asm("cvt.rna.tf32.f32 %0, %1;" : "=r"(r) : "f"(f)); return r;
}
__device__ __forceinline__ void mma_tf32(float& d0, float& d1, float& d2, float& d3,
                                         u32 a0, u32 a1, u32 a2, u32 a3,
                                         u32 b0, u32 b1) {
    asm volatile(
        "mma.sync.aligned.m16n8k8.row.col.f32.tf32.tf32.f32 "
        "{%0,%1,%2,%3}, {%4,%5,%6,%7}, {%8,%9}, {%0,%1,%2,%3};"
        : "+f"(d0), "+f"(d1), "+f"(d2), "+f"(d3)
        : "r"(a0), "r"(a1), "r"(a2), "r"(a3), "r"(b0), "r"(b1));
}
__device__ __forceinline__ float ex2(float x) {
    float y; asm("ex2.approx.f32 %0, %1;" : "=f"(y) : "f"(x)); return y;
}
__device__ __forceinline__ u32 smem_u32(const void* p) {
    u32 a;
    asm("{ .reg .u64 t; cvta.to.shared.u64 t, %1; cvt.u32.u64 %0, t; }" : "=r"(a) : "l"(p));
    return a;
}
__device__ __forceinline__ void ldsm_x4(u32& r0, u32& r1, u32& r2, u32& r3, u32 addr) {
    asm volatile("ldmatrix.sync.aligned.m8n8.x4.shared.b16 {%0,%1,%2,%3}, [%4];"
                 : "=r"(r0), "=r"(r1), "=r"(r2), "=r"(r3) : "r"(addr));
}
__device__ __forceinline__ void cpa16(u32 dst, const void* src) {
    asm volatile("cp.async.cg.shared.global [%0], [%1], 16;" :: "r"(dst), "l"(src) : "memory");
}
#define CP_COMMIT() asm volatile("cp.async.commit_group;" ::: "memory")
#define CP_WAIT0()  asm volatile("cp.async.wait_group 0;" ::: "memory")
#define CP_WAIT1()  asm volatile("cp.async.wait_group 1;" ::: "memory")

// Scratch: qkv [4096,3072] f32 (tf32-rounded values); pre-rounded x and W.
__device__ float g_qkv[(size_t)MM * N3];
__device__ float g_xc[(size_t)MM * KK];
__device__ float g_wc[(size_t)N3 * KK];

// ---------------------------------------------------------------------------
// Kernel 0: pre-pass — rna-round x and W to tf32 values (stored as f32 bits).
// ---------------------------------------------------------------------------
__global__ void cvt_prepass(const float* __restrict__ x, const float* __restrict__ W,
                            float* __restrict__ xc, float* __restrict__ wc)
{
    const size_t nx4 = (size_t)MM * KK / 4;
    const size_t nw4 = (size_t)N3 * KK / 4;
    size_t i = (size_t)blockIdx.x * blockDim.x + threadIdx.x;
    if (i < nx4) {
        float4 v = ((const float4*)x)[i];
        ((uint4*)xc)[i] = make_uint4(f2tf32(v.x), f2tf32(v.y), f2tf32(v.z), f2tf32(v.w));
    } else if (i < nx4 + nw4) {
        size_t j = i - nx4;
        float4 v = ((const float4*)W)[j];
        ((uint4*)wc)[j] = make_uint4(f2tf32(v.x), f2tf32(v.y), f2tf32(v.z), f2tf32(v.w));
    }
}

// ---------------------------------------------------------------------------
// Kernel 1: QKV GEMM, mma.sync tf32, 3-stage cp.async pipeline, chunk 8,
// prefetch issued at loop TOP (2-chunk lookahead). 2 CTAs/SM.
// ---------------------------------------------------------------------------
#define GST 12

__global__ __launch_bounds__(256, 2) void qkv_gemm_mma(
    const float* __restrict__ x,     // pre-rounded [MM, KK]
    const float* __restrict__ W,     // pre-rounded [N3, KK]
    const float* __restrict__ bias,
    float* __restrict__ C)           // [MM, N3] (tf32-rounded values)
{
    __shared__ u32 sX[3 * 128 * GST];
    __shared__ u32 sW[3 * 128 * GST];
    __shared__ float sBias[128];

    const int bm = blockIdx.y * 128;
    const int bn = blockIdx.x * 128;
    const int tid  = threadIdx.x;
    const int wid  = tid >> 5;
    const int lane = tid & 31;
    const int wm = (wid >> 2) * 64;
    const int wn = (wid & 3) * 32;
    const int lr = lane >> 2;
    const int lc = lane & 3;

    const int l_row = tid >> 1;      // 0..127
    const int l_f4  = tid & 1;       // 0..1

    const u32 sXa = smem_u32(sX);
    const u32 sWa = smem_u32(sW);
    const u32 SSZ = 128 * GST * 4;   // bytes per stage
    const u32 dX0 = sXa + (u32)((l_row * GST + l_f4 * 4) * 4);
    const u32 dW0 = sWa + (u32)((l_row * GST + l_f4 * 4) * 4);
    const float* xsrc = x + (size_t)(bm + l_row) * KK + l_f4 * 4;
    const float* wsrc = W + (size_t)(bn + l_row) * KK + l_f4 * 4;

    const int lm  = lane >> 3;
    const int lrw = lane & 7;
    const int a_row = (lm & 1) * 8 + lrw;
    const int a_col = (lm >> 1) * 4;
    const int b_nt  = lm >> 1;
    const int b_col = (lm & 1) * 4;

    float d[4][4][4];
#pragma unroll
    for (int mt = 0; mt < 4; mt++)
#pragma unroll
        for (int nt = 0; nt < 4; nt++)
#pragma unroll
            for (int r = 0; r < 4; r++) d[mt][nt][r] = 0.f;

    if (tid < 128) sBias[tid] = bias[bn + tid];

    // prologue: stages 0 and 1 in flight
#pragma unroll
    for (int s = 0; s < 2; s++) {
        cpa16(dX0 + s * SSZ, xsrc + s * 8);
        cpa16(dW0 + s * SSZ, wsrc + s * 8);
        CP_COMMIT();
    }

    const int NC = KK / 8;   // 128 chunks
#pragma unroll 3
    for (int c = 0; c < NC; c++) {
        if (c + 2 < NC) { CP_WAIT1(); } else { CP_WAIT0(); }
        __syncthreads();

        // prefetch chunk c+2 NOW (2 compute phases of lookahead)
        if (c + 2 < NC) {
            const int sn = (c + 2) % 3;
            cpa16(dX0 + sn * SSZ, xsrc + (c + 2) * 8);
            cpa16(dW0 + sn * SSZ, wsrc + (c + 2) * 8);
            CP_COMMIT();
        }

        const int st = c % 3;
        const u32 bufX = sXa + (u32)(st * SSZ);
        const u32 bufW = sWa + (u32)(st * SSZ);

        u32 af[4][4];
        u32 bf[4][2];
#pragma unroll
        for (int mt = 0; mt < 4; mt++) {
            u32 addr = bufX + (u32)(((wm + mt * 16 + a_row) * GST + a_col) * 4);
            ldsm_x4(af[mt][0], af[mt][1], af[mt][2], af[mt][3], addr);
        }
#pragma unroll
        for (int np = 0; np < 2; np++) {
            u32 addr = bufW + (u32)(((wn + (np * 2 + b_nt) * 8 + lrw) * GST + b_col) * 4);
            ldsm_x4(bf[np * 2][0], bf[np * 2][1], bf[np * 2 + 1][0], bf[np * 2 + 1][1], addr);
        }
#pragma unroll
        for (int mt = 0; mt < 4; mt++)
#pragma unroll
            for (int nt = 0; nt < 4; nt++)
                mma_tf32(d[mt][nt][0], d[mt][nt][1], d[mt][nt][2], d[mt][nt][3],
                         af[mt][0], af[mt][1], af[mt][2], af[mt][3],
                         bf[nt][0], bf[nt][1]);
    }

    // Epilogue: bias add, round to tf32 value, store.
#pragma unroll
    for (int mt = 0; mt < 4; mt++) {
        const int r0 = bm + wm + mt * 16 + lr;
#pragma unroll
        for (int nt = 0; nt < 4; nt++) {
            const int cl = wn + nt * 8 + lc * 2;
            float2 v0, v1;
            v0.x = __uint_as_float(f2tf32(d[mt][nt][0] + sBias[cl]));
            v0.y = __uint_as_float(f2tf32(d[mt][nt][1] + sBias[cl + 1]));
            v1.x = __uint_as_float(f2tf32(d[mt][nt][2] + sBias[cl]));
            v1.y = __uint_as_float(f2tf32(d[mt][nt][3] + sBias[cl + 1]));
            *(float2*)(C + (size_t)r0 * N3 + bn + cl) = v0;
            *(float2*)(C + (size_t)(r0 + 8) * N3 + bn + cl) = v1;
        }
    }
}

// ---------------------------------------------------------------------------
// Kernel 2: flash attention, mma.sync tf32, kv-tile 32, cp.async staging.
// 128 threads (4 warps), q-tile 64 -> 4 CTAs/SM for phase-desynced overlap.
// ---------------------------------------------------------------------------
#define KSTR 68
#define VSTR 72
#define KV 32

__global__ __launch_bounds__(128, 4) void attn_mma(
    const float* __restrict__ qkv,   // [MM, N3] tf32-valued
    float* __restrict__ out)         // [MM, DD]
{
    __shared__ u32 pool[2 * KV * KSTR + 2 * KV * VSTR];   // 35840 B
    u32* sV = pool + 2 * KV * KSTR;
    const u32 sKa = smem_u32(pool);
    const u32 sVa = smem_u32(sV);

    const int qtile = blockIdx.x;   // 0..31
    const int h     = blockIdx.y;
    const int b     = blockIdx.z;
    const int tid   = threadIdx.x;  // 0..127
    const int wid   = tid >> 5;     // 0..3
    const int lane  = tid & 31;
    const int lr    = lane >> 2;
    const int lc    = lane & 3;
    const int lm    = lane >> 3;
    const int lrw   = lane & 7;

    const float qs = 0.18033688011110793f;  // 0.125 * log2(e)

    // staging decomposition: 32 rows x 16 f4 per tile; 128 threads -> 4 f4 each
    const int l_row = tid >> 2;          // 0..31 (kv row)
    const int l_f4b = tid & 3;           // 0..3; i loop covers f4 = l_f4b + 4i

    // ---- Q fragments resident ----
    const int row0 = qtile * 64 + wid * 16;
    const float* q0 = qkv + ((size_t)(b * LL + row0 + lr)) * N3 + h * HD;
    const float* q1 = q0 + 8 * (size_t)N3;
    u32 qa[8][4];
#pragma unroll
    for (int kst = 0; kst < 8; kst++) {
        int kk = kst * 8;
        qa[kst][0] = f2tf32(q0[kk + lc    ] * qs);
        qa[kst][1] = f2tf32(q1[kk + lc    ] * qs);
        qa[kst][2] = f2tf32(q0[kk + lc + 4] * qs);
        qa[kst][3] = f2tf32(q1[kk + lc + 4] * qs);
    }

    float o[8][4];
#pragma unroll
    for (int dt = 0; dt < 8; dt++)
#pragma unroll
        for (int r = 0; r < 4; r++) o[dt][r] = 0.f;
    float m_a = -1e30f, m_b = -1e30f;
    float l_a = 0.f,    l_b = 0.f;

    const float* kvbase = qkv + (size_t)b * LL * N3 + DD + h * HD;
    const float* srcrow = kvbase + (size_t)l_row * N3;

    // prologue: tile 0 via cp.async into buffer 0
#pragma unroll
    for (int i = 0; i < 4; i++) {
        int f4 = l_f4b + i * 4;
        cpa16(sKa + (u32)((l_row * KSTR + f4 * 4) * 4), srcrow + f4 * 4);
        cpa16(sVa + (u32)((l_row * VSTR + f4 * 4) * 4), srcrow + DD + f4 * 4);
    }
    CP_COMMIT();

    const int NT = LL / KV;   // 64
    for (int kt = 0; kt < NT; kt++) {
        CP_WAIT0();
        __syncthreads();

        // prefetch next tile into the other buffer (1 compute phase lookahead)
        if (kt + 1 < NT) {
            const u32 kofs = (u32)(((kt + 1) & 1) * KV * KSTR * 4);
            const u32 vofs = (u32)(((kt + 1) & 1) * KV * VSTR * 4);
            const float* sr = srcrow + (size_t)((kt + 1) * KV) * N3;
#pragma unroll
            for (int i = 0; i < 4; i++) {
                int f4 = l_f4b + i * 4;
                cpa16(sKa + kofs + (u32)((l_row * KSTR + f4 * 4) * 4), sr + f4 * 4);
                cpa16(sVa + vofs + (u32)((l_row * VSTR + f4 * 4) * 4), sr + DD + f4 * 4);
            }
            CP_COMMIT();
        }

        const u32 bufK = sKa + (u32)((kt & 1) * KV * KSTR * 4);
        u32* bufV = sV + (kt & 1) * KV * VSTR;

        // ---- S = Q K^T ----
        float s[4][4];
#pragma unroll
        for (int nt = 0; nt < 4; nt++)
#pragma unroll
            for (int r = 0; r < 4; r++) s[nt][r] = 0.f;

#pragma unroll
        for (int kst = 0; kst < 8; kst++) {
            const int kk = kst * 8;
            u32 bf[4][2];
#pragma unroll
            for (int np = 0; np < 2; np++) {
                int nt0 = np * 2 + (lm >> 1);
                u32 addr = bufK + (u32)(((nt0 * 8 + lrw) * KSTR + kk + (lm & 1) * 4) * 4);
                ldsm_x4(bf[np * 2][0], bf[np * 2][1], bf[np * 2 + 1][0], bf[np * 2 + 1][1], addr);
            }
#pragma unroll
            for (int nt = 0; nt < 4; nt++)
                mma_tf32(s[nt][0], s[nt][1], s[nt][2], s[nt][3],
                         qa[kst][0], qa[kst][1], qa[kst][2], qa[kst][3],
                         bf[nt][0], bf[nt][1]);
        }

        // ---- online softmax ----
        float mx_a = -1e30f, mx_b = -1e30f;
#pragma unroll
        for (int nt = 0; nt < 4; nt++) {
            mx_a = fmaxf(mx_a, fmaxf(s[nt][0], s[nt][1]));
            mx_b = fmaxf(mx_b, fmaxf(s[nt][2], s[nt][3]));
        }
        mx_a = fmaxf(mx_a, __shfl_xor_sync(0xffffffffu, mx_a, 1));
        mx_a = fmaxf(mx_a, __shfl_xor_sync(0xffffffffu, mx_a, 2));
        mx_b = fmaxf(mx_b, __shfl_xor_sync(0xffffffffu, mx_b, 1));
        mx_b = fmaxf(mx_b, __shfl_xor_sync(0xffffffffu, mx_b, 2));

        float nm_a = fmaxf(m_a, mx_a);
        float nm_b = fmaxf(m_b, mx_b);
        float ca = ex2(m_a - nm_a);
        float cb = ex2(m_b - nm_b);
        m_a = nm_a; m_b = nm_b;
        l_a *= ca;  l_b *= cb;
#pragma unroll
        for (int dt = 0; dt < 8; dt++) {
            o[dt][0] *= ca; o[dt][1] *= ca;
            o[dt][2] *= cb; o[dt][3] *= cb;
        }

        u32 p[4][4];
#pragma unroll
        for (int nt = 0; nt < 4; nt++) {
            float p0 = ex2(s[nt][0] - m_a);
            float p1 = ex2(s[nt][1] - m_a);
            float p2 = ex2(s[nt][2] - m_b);
            float p3 = ex2(s[nt][3] - m_b);
            l_a += p0 + p1;
            l_b += p2 + p3;
            p[nt][0] = f2tf32(p0); p[nt][1] = f2tf32(p1);
            p[nt][2] = f2tf32(p2); p[nt][3] = f2tf32(p3);
        }

        // ---- O += P V (shuffle-based P relayout) ----
        const int s0 = lr * 4 + (lc >> 1);
        const int s2 = s0 + 2;
        const bool odd = (lc & 1);
#pragma unroll
        for (int jt = 0; jt < 4; jt++) {
            u32 v00 = __shfl_sync(0xffffffffu, p[jt][0], s0);
            u32 v01 = __shfl_sync(0xffffffffu, p[jt][1], s0);
            u32 v20 = __shfl_sync(0xffffffffu, p[jt][0], s2);
            u32 v21 = __shfl_sync(0xffffffffu, p[jt][1], s2);
            u32 w00 = __shfl_sync(0xffffffffu, p[jt][2], s0);
            u32 w01 = __shfl_sync(0xffffffffu, p[jt][3], s0);
            u32 w20 = __shfl_sync(0xffffffffu, p[jt][2], s2);
            u32 w21 = __shfl_sync(0xffffffffu, p[jt][3], s2);
            u32 a0 = odd ? v01 : v00;
            u32 a2 = odd ? v21 : v20;
            u32 a1 = odd ? w01 : w00;
            u32 a3 = odd ? w21 : w20;
#pragma unroll
            for (int dt = 0; dt < 8; dt++) {
                u32 b0 = bufV[(jt * 8 + lc    ) * VSTR + dt * 8 + lr];
                u32 b1 = bufV[(jt * 8 + lc + 4) * VSTR + dt * 8 + lr];
                mma_tf32(o[dt][0], o[dt][1], o[dt][2], o[dt][3],
                         a0, a1, a2, a3, b0, b1);
            }
        }
        __syncthreads();   // all warps done with buf kt before cpa overwrites it next iter
    }

    // ---- final reduce + normalize ----
    l_a += __shfl_xor_sync(0xffffffffu, l_a, 1);
    l_a += __shfl_xor_sync(0xffffffffu, l_a, 2);
    l_b += __shfl_xor_sync(0xffffffffu, l_b, 1);
    l_b += __shfl_xor_sync(0xffffffffu, l_b, 2);
    float inv_a = 1.f / l_a;
    float inv_b = 1.f / l_b;

    // ---- stage O (64 rows, stride 68) then coalesced store ----
    float* stage = (float*)pool;   // 64 x 68 floats = 17408 B <= pool
    {
        const int ra = wid * 16 + lr;
        const int rb = ra + 8;
#pragma unroll
        for (int dt = 0; dt < 8; dt++) {
            float2 va, vb;
            va.x = o[dt][0] * inv_a; va.y = o[dt][1] * inv_a;
            vb.x = o[dt][2] * inv_b; vb.y = o[dt][3] * inv_b;
            *(float2*)&stage[ra * 68 + dt * 8 + lc * 2] = va;
            *(float2*)&stage[rb * 68 + dt * 8 + lc * 2] = vb;
        }
    }
    __syncthreads();
    {
        const int cr = tid >> 4;     // 0..7
        const int cc = tid & 15;     // 0..15
#pragma unroll
        for (int pass = 0; pass < 8; pass++) {
            int row = pass * 8 + cr;
            float4 v = *(const float4*)&stage[row * 68 + cc * 4];
            *(float4*)(out + ((size_t)(b * LL + qtile * 64 + row)) * DD + h * HD + cc * 4) = v;
        }
    }
}

// ---------------------------------------------------------------------------
extern "C" void kernel_launch(void* const* d_in, const int* in_sizes, int n_in,
                              void* d_out, int out_size)
{
    const float* x    = (const float*)d_in[0];
    const float* W    = (const float*)d_in[1];
    const float* bias = (const float*)d_in[2];
    float* out = (float*)d_out;

    float *qkv, *xc, *wc;
    cudaGetSymbolAddress((void**)&qkv, g_qkv);
    cudaGetSymbolAddress((void**)&xc,  g_xc);
    cudaGetSymbolAddress((void**)&wc,  g_wc);

    const size_t nf4 = ((size_t)MM * KK + (size_t)N3 * KK) / 4;
    cvt_prepass<<<(unsigned)((nf4 + 255) / 256), 256>>>(x, W, xc, wc);

    dim3 ggrid(N3 / 128, MM / 128);  // (24, 32)
    qkv_gemm_mma<<<ggrid, 256>>>(xc, wc, bias, qkv);

    dim3 agrid(LL / 64, NH, BB);     // (32, 16, 2)
    attn_mma<<<agrid, 128>>>(qkv, out);
}

// round 14
// speedup vs baseline: 1.1456x; 1.0096x over previous
#include <cuda_runtime.h>
#include <cuda_bf16.h>
#include <cstdint>

// Problem constants
#define BB 2
#define LL 2048
#define DD 1024
#define NH 16
#define HD 64
#define MM (BB*LL)      // 4096
#define N3 (3*DD)       // 3072
#define KK DD           // 1024

typedef unsigned long long u64;
typedef unsigned int u32;

// ---- tf32 mma.sync helpers ----
__device__ __forceinline__ u32 f2tf32(float f) {
    u32 r; asm("cvt.rna.tf32.f32 %0, %1;" : "=r"(r) : "f"(f)); return r;
}
__device__ __forceinline__ void mma_tf32(float& d0, float& d1, float& d2, float& d3,
                                         u32 a0, u32 a1, u32 a2, u32 a3,
                                         u32 b0, u32 b1) {
    asm volatile(
        "mma.sync.aligned.m16n8k8.row.col.f32.tf32.tf32.f32 "
        "{%0,%1,%2,%3}, {%4,%5,%6,%7}, {%8,%9}, {%0,%1,%2,%3};"
        : "+f"(d0), "+f"(d1), "+f"(d2), "+f"(d3)
        : "r"(a0), "r"(a1), "r"(a2), "r"(a3), "r"(b0), "r"(b1));
}
__device__ __forceinline__ float ex2(float x) {
    float y; asm("ex2.approx.f32 %0, %1;" : "=f"(y) : "f"(x)); return y;
}
__device__ __forceinline__ u32 smem_u32(const void* p) {
    u32 a;
    asm("{ .reg .u64 t; cvta.to.shared.u64 t, %1; cvt.u32.u64 %0, t; }" : "=r"(a) : "l"(p));
    return a;
}
__device__ __forceinline__ void ldsm_x4(u32& r0, u32& r1, u32& r2, u32& r3, u32 addr) {
    asm volatile("ldmatrix.sync.aligned.m8n8.x4.shared.b16 {%0,%1,%2,%3}, [%4];"
                 : "=r"(r0), "=r"(r1), "=r"(r2), "=r"(r3) : "r"(addr));
}
__device__ __forceinline__ void cpa16(u32 dst, const void* src) {
    asm volatile("cp.async.cg.shared.global [%0], [%1], 16;" :: "r"(dst), "l"(src) : "memory");
}
#define CP_COMMIT() asm volatile("cp.async.commit_group;" ::: "memory")
#define CP_WAIT0()  asm volatile("cp.async.wait_group 0;" ::: "memory")
#define CP_WAIT1()  asm volatile("cp.async.wait_group 1;" ::: "memory")

// Scratch: qkv [4096,3072] f32 (tf32-rounded values); pre-rounded x and W.
__device__ float g_qkv[(size_t)MM * N3];
__device__ float g_xc[(size_t)MM * KK];
__device__ float g_wc[(size_t)N3 * KK];

// ---------------------------------------------------------------------------
// Kernel 0: pre-pass — rna-round x and W to tf32 values (stored as f32 bits).
// ---------------------------------------------------------------------------
__global__ void cvt_prepass(const float* __restrict__ x, const float* __restrict__ W,
                            float* __restrict__ xc, float* __restrict__ wc)
{
    const size_t nx4 = (size_t)MM * KK / 4;
    const size_t nw4 = (size_t)N3 * KK / 4;
    size_t i = (size_t)blockIdx.x * blockDim.x + threadIdx.x;
    if (i < nx4) {
        float4 v = ((const float4*)x)[i];
        ((uint4*)xc)[i] = make_uint4(f2tf32(v.x), f2tf32(v.y), f2tf32(v.z), f2tf32(v.w));
    } else if (i < nx4 + nw4) {
        size_t j = i - nx4;
        float4 v = ((const float4*)W)[j];
        ((uint4*)wc)[j] = make_uint4(f2tf32(v.x), f2tf32(v.y), f2tf32(v.z), f2tf32(v.w));
    }
}

// ---------------------------------------------------------------------------
// Kernel 1: QKV GEMM, mma.sync tf32, 3-stage cp.async pipeline, chunk 8,
// prefetch issued at loop TOP (2-chunk lookahead). 2 CTAs/SM. (unchanged R13)
// ---------------------------------------------------------------------------
#define GST 12

__global__ __launch_bounds__(256, 2) void qkv_gemm_mma(
    const float* __restrict__ x,     // pre-rounded [MM, KK]
    const float* __restrict__ W,     // pre-rounded [N3, KK]
    const float* __restrict__ bias,
    float* __restrict__ C)           // [MM, N3] (tf32-rounded values)
{
    __shared__ u32 sX[3 * 128 * GST];
    __shared__ u32 sW[3 * 128 * GST];
    __shared__ float sBias[128];

    const int bm = blockIdx.y * 128;
    const int bn = blockIdx.x * 128;
    const int tid  = threadIdx.x;
    const int wid  = tid >> 5;
    const int lane = tid & 31;
    const int wm = (wid >> 2) * 64;
    const int wn = (wid & 3) * 32;
    const int lr = lane >> 2;
    const int lc = lane & 3;

    const int l_row = tid >> 1;      // 0..127
    const int l_f4  = tid & 1;       // 0..1

    const u32 sXa = smem_u32(sX);
    const u32 sWa = smem_u32(sW);
    const u32 SSZ = 128 * GST * 4;
    const u32 dX0 = sXa + (u32)((l_row * GST + l_f4 * 4) * 4);
    const u32 dW0 = sWa + (u32)((l_row * GST + l_f4 * 4) * 4);
    const float* xsrc = x + (size_t)(bm + l_row) * KK + l_f4 * 4;
    const float* wsrc = W + (size_t)(bn + l_row) * KK + l_f4 * 4;

    const int lm  = lane >> 3;
    const int lrw = lane & 7;
    const int a_row = (lm & 1) * 8 + lrw;
    const int a_col = (lm >> 1) * 4;
    const int b_nt  = lm >> 1;
    const int b_col = (lm & 1) * 4;

    float d[4][4][4];
#pragma unroll
    for (int mt = 0; mt < 4; mt++)
#pragma unroll
        for (int nt = 0; nt < 4; nt++)
#pragma unroll
            for (int r = 0; r < 4; r++) d[mt][nt][r] = 0.f;

    if (tid < 128) sBias[tid] = bias[bn + tid];

#pragma unroll
    for (int s = 0; s < 2; s++) {
        cpa16(dX0 + s * SSZ, xsrc + s * 8);
        cpa16(dW0 + s * SSZ, wsrc + s * 8);
        CP_COMMIT();
    }

    const int NC = KK / 8;   // 128 chunks
#pragma unroll 3
    for (int c = 0; c < NC; c++) {
        if (c + 2 < NC) { CP_WAIT1(); } else { CP_WAIT0(); }
        __syncthreads();

        if (c + 2 < NC) {
            const int sn = (c + 2) % 3;
            cpa16(dX0 + sn * SSZ, xsrc + (c + 2) * 8);
            cpa16(dW0 + sn * SSZ, wsrc + (c + 2) * 8);
            CP_COMMIT();
        }

        const int st = c % 3;
        const u32 bufX = sXa + (u32)(st * SSZ);
        const u32 bufW = sWa + (u32)(st * SSZ);

        u32 af[4][4];
        u32 bf[4][2];
#pragma unroll
        for (int mt = 0; mt < 4; mt++) {
            u32 addr = bufX + (u32)(((wm + mt * 16 + a_row) * GST + a_col) * 4);
            ldsm_x4(af[mt][0], af[mt][1], af[mt][2], af[mt][3], addr);
        }
#pragma unroll
        for (int np = 0; np < 2; np++) {
            u32 addr = bufW + (u32)(((wn + (np * 2 + b_nt) * 8 + lrw) * GST + b_col) * 4);
            ldsm_x4(bf[np * 2][0], bf[np * 2][1], bf[np * 2 + 1][0], bf[np * 2 + 1][1], addr);
        }
#pragma unroll
        for (int mt = 0; mt < 4; mt++)
#pragma unroll
            for (int nt = 0; nt < 4; nt++)
                mma_tf32(d[mt][nt][0], d[mt][nt][1], d[mt][nt][2], d[mt][nt][3],
                         af[mt][0], af[mt][1], af[mt][2], af[mt][3],
                         bf[nt][0], bf[nt][1]);
    }

#pragma unroll
    for (int mt = 0; mt < 4; mt++) {
        const int r0 = bm + wm + mt * 16 + lr;
#pragma unroll
        for (int nt = 0; nt < 4; nt++) {
            const int cl = wn + nt * 8 + lc * 2;
            float2 v0, v1;
            v0.x = __uint_as_float(f2tf32(d[mt][nt][0] + sBias[cl]));
            v0.y = __uint_as_float(f2tf32(d[mt][nt][1] + sBias[cl + 1]));
            v1.x = __uint_as_float(f2tf32(d[mt][nt][2] + sBias[cl]));
            v1.y = __uint_as_float(f2tf32(d[mt][nt][3] + sBias[cl + 1]));
            *(float2*)(C + (size_t)r0 * N3 + bn + cl) = v0;
            *(float2*)(C + (size_t)(r0 + 8) * N3 + bn + cl) = v1;
        }
    }
}

// ---------------------------------------------------------------------------
// Kernel 2: flash attention, mma.sync tf32, kv-tile 32, cp.async staging.
// 128 threads (4 warps), q-tile 128: 2 m-tiles (32 rows) per warp so every
// K-LDSM and V-LDS B-fragment feeds 2x the MMAs.
// ---------------------------------------------------------------------------
#define KSTR 68
#define VSTR 72
#define KV 32

__global__ __launch_bounds__(128) void attn_mma(
    const float* __restrict__ qkv,   // [MM, N3] tf32-valued
    float* __restrict__ out)         // [MM, DD]
{
    __shared__ u32 pool[2 * KV * KSTR + 2 * KV * VSTR];   // 35840 B
    u32* sV = pool + 2 * KV * KSTR;
    const u32 sKa = smem_u32(pool);
    const u32 sVa = smem_u32(sV);

    const int qtile = blockIdx.x;   // 0..15
    const int h     = blockIdx.y;
    const int b     = blockIdx.z;
    const int tid   = threadIdx.x;  // 0..127
    const int wid   = tid >> 5;     // 0..3
    const int lane  = tid & 31;
    const int lr    = lane >> 2;
    const int lc    = lane & 3;
    const int lm    = lane >> 3;
    const int lrw   = lane & 7;

    const float qs = 0.18033688011110793f;  // 0.125 * log2(e)

    const int l_row = tid >> 2;          // 0..31 (kv row)
    const int l_f4b = tid & 3;           // 0..3; f4 = l_f4b + 4i

    // ---- Q fragments resident: 2 m-tiles of 16 rows each ----
    u32 qa[2][8][4];
#pragma unroll
    for (int mt = 0; mt < 2; mt++) {
        const int row0 = qtile * 128 + wid * 32 + mt * 16;
        const float* q0 = qkv + ((size_t)(b * LL + row0 + lr)) * N3 + h * HD;
        const float* q1 = q0 + 8 * (size_t)N3;
#pragma unroll
        for (int kst = 0; kst < 8; kst++) {
            int kk = kst * 8;
            qa[mt][kst][0] = f2tf32(q0[kk + lc    ] * qs);
            qa[mt][kst][1] = f2tf32(q1[kk + lc    ] * qs);
            qa[mt][kst][2] = f2tf32(q0[kk + lc + 4] * qs);
            qa[mt][kst][3] = f2tf32(q1[kk + lc + 4] * qs);
        }
    }

    float o[2][8][4];
#pragma unroll
    for (int mt = 0; mt < 2; mt++)
#pragma unroll
        for (int dt = 0; dt < 8; dt++)
#pragma unroll
            for (int r = 0; r < 4; r++) o[mt][dt][r] = 0.f;
    float m_a[2] = {-1e30f, -1e30f}, m_b[2] = {-1e30f, -1e30f};
    float l_a[2] = {0.f, 0.f},       l_b[2] = {0.f, 0.f};

    const float* kvbase = qkv + (size_t)b * LL * N3 + DD + h * HD;
    const float* srcrow = kvbase + (size_t)l_row * N3;

    // prologue: tile 0 via cp.async into buffer 0
#pragma unroll
    for (int i = 0; i < 4; i++) {
        int f4 = l_f4b + i * 4;
        cpa16(sKa + (u32)((l_row * KSTR + f4 * 4) * 4), srcrow + f4 * 4);
        cpa16(sVa + (u32)((l_row * VSTR + f4 * 4) * 4), srcrow + DD + f4 * 4);
    }
    CP_COMMIT();

    const int NT = LL / KV;   // 64
    for (int kt = 0; kt < NT; kt++) {
        CP_WAIT0();
        __syncthreads();

        if (kt + 1 < NT) {
            const u32 kofs = (u32)(((kt + 1) & 1) * KV * KSTR * 4);
            const u32 vofs = (u32)(((kt + 1) & 1) * KV * VSTR * 4);
            const float* sr = srcrow + (size_t)((kt + 1) * KV) * N3;
#pragma unroll
            for (int i = 0; i < 4; i++) {
                int f4 = l_f4b + i * 4;
                cpa16(sKa + kofs + (u32)((l_row * KSTR + f4 * 4) * 4), sr + f4 * 4);
                cpa16(sVa + vofs + (u32)((l_row * VSTR + f4 * 4) * 4), sr + DD + f4 * 4);
            }
            CP_COMMIT();
        }

        const u32 bufK = sKa + (u32)((kt & 1) * KV * KSTR * 4);
        u32* bufV = sV + (kt & 1) * KV * VSTR;

        // ---- S = Q K^T : K frags shared across both m-tiles ----
        float s[2][4][4];
#pragma unroll
        for (int mt = 0; mt < 2; mt++)
#pragma unroll
            for (int nt = 0; nt < 4; nt++)
#pragma unroll
                for (int r = 0; r < 4; r++) s[mt][nt][r] = 0.f;

#pragma unroll
        for (int kst = 0; kst < 8; kst++) {
            const int kk = kst * 8;
            u32 bf[4][2];
#pragma unroll
            for (int np = 0; np < 2; np++) {
                int nt0 = np * 2 + (lm >> 1);
                u32 addr = bufK + (u32)(((nt0 * 8 + lrw) * KSTR + kk + (lm & 1) * 4) * 4);
                ldsm_x4(bf[np * 2][0], bf[np * 2][1], bf[np * 2 + 1][0], bf[np * 2 + 1][1], addr);
            }
#pragma unroll
            for (int mt = 0; mt < 2; mt++)
#pragma unroll
                for (int nt = 0; nt < 4; nt++)
                    mma_tf32(s[mt][nt][0], s[mt][nt][1], s[mt][nt][2], s[mt][nt][3],
                             qa[mt][kst][0], qa[mt][kst][1], qa[mt][kst][2], qa[mt][kst][3],
                             bf[nt][0], bf[nt][1]);
        }

        // ---- online softmax per m-tile; p in A-operand u32 form ----
        u32 p[2][4][4];
#pragma unroll
        for (int mt = 0; mt < 2; mt++) {
            float mx_a = -1e30f, mx_b = -1e30f;
#pragma unroll
            for (int nt = 0; nt < 4; nt++) {
                mx_a = fmaxf(mx_a, fmaxf(s[mt][nt][0], s[mt][nt][1]));
                mx_b = fmaxf(mx_b, fmaxf(s[mt][nt][2], s[mt][nt][3]));
            }
            mx_a = fmaxf(mx_a, __shfl_xor_sync(0xffffffffu, mx_a, 1));
            mx_a = fmaxf(mx_a, __shfl_xor_sync(0xffffffffu, mx_a, 2));
            mx_b = fmaxf(mx_b, __shfl_xor_sync(0xffffffffu, mx_b, 1));
            mx_b = fmaxf(mx_b, __shfl_xor_sync(0xffffffffu, mx_b, 2));

            float nm_a = fmaxf(m_a[mt], mx_a);
            float nm_b = fmaxf(m_b[mt], mx_b);
            float ca = ex2(m_a[mt] - nm_a);
            float cb = ex2(m_b[mt] - nm_b);
            m_a[mt] = nm_a; m_b[mt] = nm_b;
            l_a[mt] *= ca;  l_b[mt] *= cb;
#pragma unroll
            for (int dt = 0; dt < 8; dt++) {
                o[mt][dt][0] *= ca; o[mt][dt][1] *= ca;
                o[mt][dt][2] *= cb; o[mt][dt][3] *= cb;
            }
#pragma unroll
            for (int nt = 0; nt < 4; nt++) {
                float p0 = ex2(s[mt][nt][0] - m_a[mt]);
                float p1 = ex2(s[mt][nt][1] - m_a[mt]);
                float p2 = ex2(s[mt][nt][2] - m_b[mt]);
                float p3 = ex2(s[mt][nt][3] - m_b[mt]);
                l_a[mt] += p0 + p1;
                l_b[mt] += p2 + p3;
                p[mt][nt][0] = f2tf32(p0); p[mt][nt][1] = f2tf32(p1);
                p[mt][nt][2] = f2tf32(p2); p[mt][nt][3] = f2tf32(p3);
            }
        }

        // ---- O += P V : V frags shared across both m-tiles ----
        const int s0 = lr * 4 + (lc >> 1);
        const int s2 = s0 + 2;
        const bool odd = (lc & 1);
#pragma unroll
        for (int jt = 0; jt < 4; jt++) {
            u32 A[2][4];
#pragma unroll
            for (int mt = 0; mt < 2; mt++) {
                u32 v00 = __shfl_sync(0xffffffffu, p[mt][jt][0], s0);
                u32 v01 = __shfl_sync(0xffffffffu, p[mt][jt][1], s0);
                u32 v20 = __shfl_sync(0xffffffffu, p[mt][jt][0], s2);
                u32 v21 = __shfl_sync(0xffffffffu, p[mt][jt][1], s2);
                u32 w00 = __shfl_sync(0xffffffffu, p[mt][jt][2], s0);
                u32 w01 = __shfl_sync(0xffffffffu, p[mt][jt][3], s0);
                u32 w20 = __shfl_sync(0xffffffffu, p[mt][jt][2], s2);
                u32 w21 = __shfl_sync(0xffffffffu, p[mt][jt][3], s2);
                A[mt][0] = odd ? v01 : v00;
                A[mt][2] = odd ? v21 : v20;
                A[mt][1] = odd ? w01 : w00;
                A[mt][3] = odd ? w21 : w20;
            }
#pragma unroll
            for (int dt = 0; dt < 8; dt++) {
                u32 b0 = bufV[(jt * 8 + lc    ) * VSTR + dt * 8 + lr];
                u32 b1 = bufV[(jt * 8 + lc + 4) * VSTR + dt * 8 + lr];
                mma_tf32(o[0][dt][0], o[0][dt][1], o[0][dt][2], o[0][dt][3],
                         A[0][0], A[0][1], A[0][2], A[0][3], b0, b1);
                mma_tf32(o[1][dt][0], o[1][dt][1], o[1][dt][2], o[1][dt][3],
                         A[1][0], A[1][1], A[1][2], A[1][3], b0, b1);
            }
        }
        __syncthreads();   // all warps done with buf kt before cpa overwrites it
    }

    // ---- final reduce + normalize ----
    float inv_a[2], inv_b[2];
#pragma unroll
    for (int mt = 0; mt < 2; mt++) {
        l_a[mt] += __shfl_xor_sync(0xffffffffu, l_a[mt], 1);
        l_a[mt] += __shfl_xor_sync(0xffffffffu, l_a[mt], 2);
        l_b[mt] += __shfl_xor_sync(0xffffffffu, l_b[mt], 1);
        l_b[mt] += __shfl_xor_sync(0xffffffffu, l_b[mt], 2);
        inv_a[mt] = 1.f / l_a[mt];
        inv_b[mt] = 1.f / l_b[mt];
    }

    // ---- stage O (128 rows, stride 68 = 34816 B <= pool) then store ----
    float* stage = (float*)pool;
    {
#pragma unroll
        for (int mt = 0; mt < 2; mt++) {
            const int ra = wid * 32 + mt * 16 + lr;
            const int rb = ra + 8;
#pragma unroll
            for (int dt = 0; dt < 8; dt++) {
                float2 va, vb;
                va.x = o[mt][dt][0] * inv_a[mt]; va.y = o[mt][dt][1] * inv_a[mt];
                vb.x = o[mt][dt][2] * inv_b[mt]; vb.y = o[mt][dt][3] * inv_b[mt];
                *(float2*)&stage[ra * 68 + dt * 8 + lc * 2] = va;
                *(float2*)&stage[rb * 68 + dt * 8 + lc * 2] = vb;
            }
        }
    }
    __syncthreads();
    {
        const int cr = tid >> 4;     // 0..7
        const int cc = tid & 15;     // 0..15
#pragma unroll
        for (int pass = 0; pass < 16; pass++) {
            int row = pass * 8 + cr;
            float4 v = *(const float4*)&stage[row * 68 + cc * 4];
            *(float4*)(out + ((size_t)(b * LL + qtile * 128 + row)) * DD + h * HD + cc * 4) = v;
        }
    }
}

// ---------------------------------------------------------------------------
extern "C" void kernel_launch(void* const* d_in, const int* in_sizes, int n_in,
                              void* d_out, int out_size)
{
    const float* x    = (const float*)d_in[0];
    const float* W    = (const float*)d_in[1];
    const float* bias = (const float*)d_in[2];
    float* out = (float*)d_out;

    float *qkv, *xc, *wc;
    cudaGetSymbolAddress((void**)&qkv, g_qkv);
    cudaGetSymbolAddress((void**)&xc,  g_xc);
    cudaGetSymbolAddress((void**)&wc,  g_wc);

    const size_t nf4 = ((size_t)MM * KK + (size_t)N3 * KK) / 4;
    cvt_prepass<<<(unsigned)((nf4 + 255) / 256), 256>>>(x, W, xc, wc);

    dim3 ggrid(N3 / 128, MM / 128);  // (24, 32)
    qkv_gemm_mma<<<ggrid, 256>>>(xc, wc, bias, qkv);

    dim3 agrid(LL / 128, NH, BB);    // (16, 16, 2)
    attn_mma<<<agrid, 128>>>(qkv, out);
}